// round 1
// baseline (speedup 1.0000x reference)
#include <cuda_runtime.h>
#include <cstdint>

// Problem shape (fixed by reference setup_inputs)
#define BATCH 32
#define H 1024
#define W 1024
#define TILE_H 64
#define HALO 2
#define LROWS (TILE_H + 2*HALO)   // 68 loaded rows per tile
#define WORDS (W/32)              // 32 packed words per row
#define THREADS 256
#define NWARPS (THREADS/32)

// Global accumulators (scratch via __device__ globals per harness rules)
__device__ double g_sum_w;          // weighted loss sum
__device__ double g_sum_u;          // unweighted loss sum
__device__ unsigned g_or;           // OR of all target bits  (any 1 -> max==1)
__device__ unsigned g_and;          // AND of all target bits (any 0 -> min==0)

__global__ void init_kernel() {
    g_sum_w = 0.0;
    g_sum_u = 0.0;
    g_or = 0u;
    g_and = 0xFFFFFFFFu;
}

__global__ __launch_bounds__(THREADS)
void loss_kernel(const float* __restrict__ pred, const float* __restrict__ target) {
    __shared__ unsigned or_sh[LROWS][WORDS];   // packed bits, 0-padded rows (dilate identity)
    __shared__ unsigned and_sh[LROWS][WORDS];  // packed bits, 1-padded rows (erode identity)
    __shared__ unsigned e_sh[TILE_H][WORDS];   // edge bits (weight = 0.1 where set)
    __shared__ float   warp_w[NWARPS], warp_u[NWARPS];
    __shared__ unsigned warp_or[NWARPS], warp_and[NWARPS];

    const int tid  = threadIdx.x;
    const int lane = tid & 31;
    const int wid  = tid >> 5;

    const int batch = blockIdx.y;
    const int r0    = blockIdx.x * TILE_H;

    const float* tgt_img  = target + (size_t)batch * H * W;
    const float* pred_img = pred   + (size_t)batch * H * W;

    // ---------------- Phase 1: load target once, binarize + bit-pack ----------------
    // One warp per 32-pixel word: coalesced 128B load + ballot.
    for (int widx = wid; widx < LROWS * WORDS; widx += NWARPS) {
        int lr = widx >> 5;        // local row 0..LROWS-1
        int w  = widx & 31;        // word in row
        int gr = r0 + lr - HALO;   // global row
        bool rv = (gr >= 0) && (gr < H);
        float v = rv ? __ldg(&tgt_img[(size_t)gr * W + w * 32 + lane]) : 0.0f;
        unsigned bits = __ballot_sync(0xFFFFFFFFu, v > 0.5f);
        if (lane == 0) {
            or_sh[lr][w]  = rv ? bits : 0u;
            and_sh[lr][w] = rv ? bits : 0xFFFFFFFFu;
        }
    }
    __syncthreads();

    // ---------------- Phase 2: 5x5 morphological gradient on packed bits -------------
    // warp handles one output row per iteration; lane == word index.
    unsigned acc_or = 0u, acc_and = 0xFFFFFFFFu;
    for (int r = wid; r < TILE_H; r += NWARPS) {
        int lr = r + HALO;
        // vertical 5-row OR / AND
        unsigned vo = or_sh[lr-2][lane] | or_sh[lr-1][lane] | or_sh[lr][lane]
                    | or_sh[lr+1][lane] | or_sh[lr+2][lane];
        unsigned va = and_sh[lr-2][lane] & and_sh[lr-1][lane] & and_sh[lr][lane]
                    & and_sh[lr+1][lane] & and_sh[lr+2][lane];
        // neighbor words for horizontal window (lane-1 = lower cols, lane+1 = higher cols)
        unsigned lo = __shfl_up_sync  (0xFFFFFFFFu, vo, 1);
        unsigned ro = __shfl_down_sync(0xFFFFFFFFu, vo, 1);
        unsigned la = __shfl_up_sync  (0xFFFFFFFFu, va, 1);
        unsigned ra = __shfl_down_sync(0xFFFFFFFFu, va, 1);
        if (lane == 0)  { lo = 0u; la = 0xFFFFFFFFu; }   // image left edge
        if (lane == 31) { ro = 0u; ra = 0xFFFFFFFFu; }   // image right edge
        // horizontal +-2 window: bit j -> OR/AND of bits j-2..j+2 across word boundaries
        unsigned orr = vo
                     | __funnelshift_r(vo, ro, 1) | __funnelshift_r(vo, ro, 2)
                     | __funnelshift_l(lo, vo, 1) | __funnelshift_l(lo, vo, 2);
        unsigned ann = va
                     & __funnelshift_r(va, ra, 1) & __funnelshift_r(va, ra, 2)
                     & __funnelshift_l(la, va, 1) & __funnelshift_l(la, va, 2);
        e_sh[r][lane] = orr & ~ann;   // mixed window -> weight 0.1

        unsigned tword = or_sh[lr][lane];   // interior rows: exact packed target
        acc_or  |= tword;
        acc_and &= tword;
    }
    acc_or  = __reduce_or_sync (0xFFFFFFFFu, acc_or);
    acc_and = __reduce_and_sync(0xFFFFFFFFu, acc_and);
    if (lane == 0) { warp_or[wid] = acc_or; warp_and[wid] = acc_and; }
    __syncthreads();   // publishes e_sh + warp_or/and

    // ---------------- Phase 3: loss + weighted accumulation (pred read once) ---------
    float sum_w = 0.f, sum_u = 0.f;
    #pragma unroll 4
    for (int r = 0; r < TILE_H; r++) {
        // 256 float4 groups per row; c4 == tid -> fully coalesced
        float4 p4 = reinterpret_cast<const float4*>(pred_img + (size_t)(r0 + r) * W)[tid];
        unsigned e = e_sh[r][tid >> 3];
        unsigned t = or_sh[r + HALO][tid >> 3];
        int sh = (tid & 7) * 4;
        float p[4] = {p4.x, p4.y, p4.z, p4.w};
        #pragma unroll
        for (int j = 0; j < 4; j++) {
            float x  = p[j];
            // stable softplus: max(x,0) + log(1 + exp(-|x|))
            float sp = fmaxf(x, 0.0f) + __logf(1.0f + __expf(-fabsf(x)));
            float tb = (float)((t >> (sh + j)) & 1u);
            float l  = sp - x * tb;
            sum_u += l;
            sum_w += ((e >> (sh + j)) & 1u) ? 0.1f * l : l;
        }
    }

    // ---------------- Block reduction + one global atomic per block -------------------
    #pragma unroll
    for (int o = 16; o; o >>= 1) {
        sum_w += __shfl_xor_sync(0xFFFFFFFFu, sum_w, o);
        sum_u += __shfl_xor_sync(0xFFFFFFFFu, sum_u, o);
    }
    if (lane == 0) { warp_w[wid] = sum_w; warp_u[wid] = sum_u; }
    __syncthreads();
    if (wid == 0) {
        float    bw = (lane < NWARPS) ? warp_w[lane]   : 0.f;
        float    bu = (lane < NWARPS) ? warp_u[lane]   : 0.f;
        unsigned bo = (lane < NWARPS) ? warp_or[lane]  : 0u;
        unsigned ba = (lane < NWARPS) ? warp_and[lane] : 0xFFFFFFFFu;
        #pragma unroll
        for (int o = 4; o; o >>= 1) {
            bw += __shfl_xor_sync(0xFFFFFFFFu, bw, o);
            bu += __shfl_xor_sync(0xFFFFFFFFu, bu, o);
            bo |= __shfl_xor_sync(0xFFFFFFFFu, bo, o);
            ba &= __shfl_xor_sync(0xFFFFFFFFu, ba, o);
        }
        if (lane == 0) {
            atomicAdd(&g_sum_w, (double)bw);
            atomicAdd(&g_sum_u, (double)bu);
            atomicOr (&g_or,  bo);
            atomicAnd(&g_and, ba);
        }
    }
}

__global__ void final_kernel(float* __restrict__ out) {
    // cond: target.max()==1 (some bit set) AND target.min()==0 (some bit clear)
    bool cond = (g_or != 0u) && (g_and != 0xFFFFFFFFu);
    double s = cond ? g_sum_w : g_sum_u;
    out[0] = (float)(s / (double)((size_t)BATCH * H * W));
}

extern "C" void kernel_launch(void* const* d_in, const int* in_sizes, int n_in,
                              void* d_out, int out_size) {
    const float* pred   = (const float*)d_in[0];
    const float* target = (const float*)d_in[1];
    float* out = (float*)d_out;

    init_kernel<<<1, 1>>>();
    dim3 grid(H / TILE_H, BATCH);   // 16 x 32 = 512 blocks
    loss_kernel<<<grid, THREADS>>>(pred, target);
    final_kernel<<<1, 1>>>(out);
}

// round 5
// speedup vs baseline: 1.2213x; 1.2213x over previous
#include <cuda_runtime.h>
#include <cstdint>

// Problem shape (fixed by reference setup_inputs)
#define BATCH 32
#define H 1024
#define W 1024
#define TILE_H 64
#define HALO 2
#define LROWS (TILE_H + 2*HALO)   // 68 loaded rows per tile
#define WORDS (W/32)              // 32 packed words per row
#define THREADS 256
#define NWARPS (THREADS/32)
#define NBLOCKS ((H/TILE_H)*BATCH)   // 512

// Per-block partials (written by every block on every call -> no init needed)
__device__ float    g_pw[NBLOCKS];   // weighted loss partial
__device__ float    g_pu[NBLOCKS];   // unweighted loss partial
__device__ unsigned g_po[NBLOCKS];   // OR of target bits in block
__device__ unsigned g_pa[NBLOCKS];   // AND of target bits in block

__global__ __launch_bounds__(THREADS)
void loss_kernel(const float* __restrict__ pred, const float* __restrict__ target) {
    __shared__ unsigned or_sh[LROWS][WORDS];   // packed target bits, 0-padded halo (dilate identity)
    __shared__ unsigned and_sh[LROWS][WORDS];  // packed target bits, 1-padded halo (erode identity)
    __shared__ unsigned e_sh[TILE_H][WORDS];   // edge bits (weight 0.1 where set)
    __shared__ float    warp_w[NWARPS], warp_u[NWARPS];
    __shared__ unsigned warp_or[NWARPS], warp_and[NWARPS];

    const int tid  = threadIdx.x;
    const int lane = tid & 31;
    const int wid  = tid >> 5;

    const int batch = blockIdx.y;
    const int r0    = blockIdx.x * TILE_H;

    const float* tgt_img  = target + (size_t)batch * H * W;
    const float* pred_img = pred   + (size_t)batch * H * W;

    const unsigned gmask = 0xFFu << ((lane >> 3) * 8);  // 8-lane pack group
    const int word = tid >> 3;          // which 32-bit word this thread's 4 pixels fall in
    const int sh   = (tid & 7) * 4;     // bit offset within word

    // ---------------- Phase 1: vectorized target load + bit-pack ----------------
    // One full row per 256-thread sweep (256 x float4 = 1024 px). 68 independent
    // float4 loads per thread -> high MLP; pack via 8-lane REDUX off the load path.
    #pragma unroll 4
    for (int lr = 0; lr < LROWS; lr++) {
        int gr = r0 + lr - HALO;
        bool rv = (gr >= 0) && (gr < H);
        unsigned nib = 0u;
        if (rv) {
            float4 t4 = reinterpret_cast<const float4*>(tgt_img + (size_t)gr * W)[tid];
            nib = (unsigned)(t4.x > 0.5f)
                | ((unsigned)(t4.y > 0.5f) << 1)
                | ((unsigned)(t4.z > 0.5f) << 2)
                | ((unsigned)(t4.w > 0.5f) << 3);
        }
        unsigned w32 = __reduce_or_sync(gmask, nib << sh);
        if ((lane & 7) == 0) {
            or_sh [lr][word] = rv ? w32 : 0u;
            and_sh[lr][word] = rv ? w32 : 0xFFFFFFFFu;
        }
    }
    __syncthreads();

    // ---------------- Phase 2: 5x5 morphological gradient on packed bits -------------
    unsigned acc_or = 0u, acc_and = 0xFFFFFFFFu;
    for (int r = wid; r < TILE_H; r += NWARPS) {
        int lr = r + HALO;
        unsigned vo = or_sh[lr-2][lane] | or_sh[lr-1][lane] | or_sh[lr][lane]
                    | or_sh[lr+1][lane] | or_sh[lr+2][lane];
        unsigned va = and_sh[lr-2][lane] & and_sh[lr-1][lane] & and_sh[lr][lane]
                    & and_sh[lr+1][lane] & and_sh[lr+2][lane];
        unsigned lo = __shfl_up_sync  (0xFFFFFFFFu, vo, 1);
        unsigned ro = __shfl_down_sync(0xFFFFFFFFu, vo, 1);
        unsigned la = __shfl_up_sync  (0xFFFFFFFFu, va, 1);
        unsigned ra = __shfl_down_sync(0xFFFFFFFFu, va, 1);
        if (lane == 0)  { lo = 0u; la = 0xFFFFFFFFu; }   // image left edge
        if (lane == 31) { ro = 0u; ra = 0xFFFFFFFFu; }   // image right edge
        unsigned orr = vo
                     | __funnelshift_r(vo, ro, 1) | __funnelshift_r(vo, ro, 2)
                     | __funnelshift_l(lo, vo, 1) | __funnelshift_l(lo, vo, 2);
        unsigned ann = va
                     & __funnelshift_r(va, ra, 1) & __funnelshift_r(va, ra, 2)
                     & __funnelshift_l(la, va, 1) & __funnelshift_l(la, va, 2);
        e_sh[r][lane] = orr & ~ann;

        unsigned tword = or_sh[lr][lane];
        acc_or  |= tword;
        acc_and &= tword;
    }
    acc_or  = __reduce_or_sync (0xFFFFFFFFu, acc_or);
    acc_and = __reduce_and_sync(0xFFFFFFFFu, acc_and);
    if (lane == 0) { warp_or[wid] = acc_or; warp_and[wid] = acc_and; }
    __syncthreads();   // publishes e_sh + warp_or/and

    // ---------------- Phase 3: loss + weighted accumulation (pred read once) ---------
    float sum_w = 0.f, sum_u = 0.f;
    #pragma unroll 4
    for (int r = 0; r < TILE_H; r++) {
        float4 p4 = reinterpret_cast<const float4*>(pred_img + (size_t)(r0 + r) * W)[tid];
        unsigned e = e_sh[r][word];
        unsigned t = or_sh[r + HALO][word];
        float p[4] = {p4.x, p4.y, p4.z, p4.w};
        #pragma unroll
        for (int j = 0; j < 4; j++) {
            float x  = p[j];
            // stable softplus: max(x,0) + log(1 + exp(-|x|))
            float sp = fmaxf(x, 0.0f) + __logf(1.0f + __expf(-fabsf(x)));
            float tb = (float)((t >> (sh + j)) & 1u);
            float l  = sp - x * tb;
            float wgt = 1.0f - 0.9f * (float)((e >> (sh + j)) & 1u);
            sum_u += l;
            sum_w = fmaf(l, wgt, sum_w);
        }
    }

    // ---------------- Block reduction -> per-block partials ---------------------------
    #pragma unroll
    for (int o = 16; o; o >>= 1) {
        sum_w += __shfl_xor_sync(0xFFFFFFFFu, sum_w, o);
        sum_u += __shfl_xor_sync(0xFFFFFFFFu, sum_u, o);
    }
    if (lane == 0) { warp_w[wid] = sum_w; warp_u[wid] = sum_u; }
    __syncthreads();
    if (wid == 0) {
        float    bw = (lane < NWARPS) ? warp_w[lane]   : 0.f;
        float    bu = (lane < NWARPS) ? warp_u[lane]   : 0.f;
        unsigned bo = (lane < NWARPS) ? warp_or[lane]  : 0u;
        unsigned ba = (lane < NWARPS) ? warp_and[lane] : 0xFFFFFFFFu;
        #pragma unroll
        for (int o = 4; o; o >>= 1) {
            bw += __shfl_xor_sync(0xFFFFFFFFu, bw, o);
            bu += __shfl_xor_sync(0xFFFFFFFFu, bu, o);
            bo |= __shfl_xor_sync(0xFFFFFFFFu, bo, o);
            ba &= __shfl_xor_sync(0xFFFFFFFFu, ba, o);
        }
        if (lane == 0) {
            int bidx = blockIdx.y * gridDim.x + blockIdx.x;
            g_pw[bidx] = bw;
            g_pu[bidx] = bu;
            g_po[bidx] = bo;
            g_pa[bidx] = ba;
        }
    }
}

__global__ __launch_bounds__(NBLOCKS)
void final_kernel(float* __restrict__ out) {
    __shared__ double sw_sh[NBLOCKS/32], su_sh[NBLOCKS/32];
    __shared__ unsigned o_sh[NBLOCKS/32], a_sh[NBLOCKS/32];
    const int tid = threadIdx.x, lane = tid & 31, wid = tid >> 5;

    double   sw = (double)g_pw[tid];
    double   su = (double)g_pu[tid];
    unsigned bo = g_po[tid];
    unsigned ba = g_pa[tid];
    #pragma unroll
    for (int o = 16; o; o >>= 1) {
        sw += __shfl_xor_sync(0xFFFFFFFFu, sw, o);
        su += __shfl_xor_sync(0xFFFFFFFFu, su, o);
        bo |= __shfl_xor_sync(0xFFFFFFFFu, bo, o);
        ba &= __shfl_xor_sync(0xFFFFFFFFu, ba, o);
    }
    if (lane == 0) { sw_sh[wid] = sw; su_sh[wid] = su; o_sh[wid] = bo; a_sh[wid] = ba; }
    __syncthreads();
    if (wid == 0) {
        const int nw = NBLOCKS / 32;   // 16
        double   w = (lane < nw) ? sw_sh[lane] : 0.0;
        double   u = (lane < nw) ? su_sh[lane] : 0.0;
        unsigned o = (lane < nw) ? o_sh[lane]  : 0u;
        unsigned a = (lane < nw) ? a_sh[lane]  : 0xFFFFFFFFu;
        #pragma unroll
        for (int off = 8; off; off >>= 1) {
            w += __shfl_xor_sync(0xFFFFFFFFu, w, off);
            u += __shfl_xor_sync(0xFFFFFFFFu, u, off);
            o |= __shfl_xor_sync(0xFFFFFFFFu, o, off);
            a &= __shfl_xor_sync(0xFFFFFFFFu, a, off);
        }
        if (lane == 0) {
            bool cond = (o != 0u) && (a != 0xFFFFFFFFu);
            double s = cond ? w : u;
            out[0] = (float)(s / (double)((size_t)BATCH * H * W));
        }
    }
}

extern "C" void kernel_launch(void* const* d_in, const int* in_sizes, int n_in,
                              void* d_out, int out_size) {
    const float* pred   = (const float*)d_in[0];
    const float* target = (const float*)d_in[1];
    float* out = (float*)d_out;

    dim3 grid(H / TILE_H, BATCH);   // 16 x 32 = 512 blocks
    loss_kernel<<<grid, THREADS>>>(pred, target);
    final_kernel<<<1, NBLOCKS>>>(out);
}